// round 3
// baseline (speedup 1.0000x reference)
#include <cuda_runtime.h>
#include <cstdint>

// Problem constants (CompletePatchReadout): B=64, T=12, P=128, F=128, H=12, MAXC=48
#define Bdim   64
#define Tdim   12
#define Pdim   128
#define Fdim   128
#define Hdim   12
#define MAXC   48
#define Ddim   (Tdim * Fdim)        // 1536  (K)
#define NCdim  (MAXC * Hdim)        // 576   (GEMM N)
#define NNODES 4356                  // sum of COUNTS (sentinel value in node_map)

#define TM 64          // M tile = all batches
#define TN 64          // N tile (576 = 9 * 64)
#define TK 16          // K chunk (two k8 mma steps)
#define NKC (Ddim / TK)   // 96
#define NTHREADS 256      // 8 warps: 2 (M) x 4 (N)
#define SSTR 68           // smem row stride (floats): 16B-aligned, spreads banks

// ---- tf32 split: v ~= hi + lo, each exactly representable in tf32 ----
__device__ __forceinline__ void split_tf32(float v, unsigned& hi, unsigned& lo) {
    asm("cvt.rna.tf32.f32 %0, %1;" : "=r"(hi) : "f"(v));
    float rem = v - __uint_as_float(hi);
    asm("cvt.rna.tf32.f32 %0, %1;" : "=r"(lo) : "f"(rem));
}

__device__ __forceinline__ void mma_tf32(float* c, const unsigned* a, const unsigned* b) {
    asm volatile(
        "mma.sync.aligned.m16n8k8.row.col.f32.tf32.tf32.f32 "
        "{%0,%1,%2,%3}, {%4,%5,%6,%7}, {%8,%9}, {%0,%1,%2,%3};"
        : "+f"(c[0]), "+f"(c[1]), "+f"(c[2]), "+f"(c[3])
        : "r"(a[0]), "r"(a[1]), "r"(a[2]), "r"(a[3]), "r"(b[0]), "r"(b[1]));
}

__global__ __launch_bounds__(NTHREADS, 1)
void patch_readout_tf32x3_kernel(
    const float* __restrict__ x,        // [B, T, P, F]
    const float* __restrict__ W,        // [P, D, MAXC, H] == [P][1536][576]
    const float* __restrict__ bias,     // [P, MAXC, H]    == [P][576]
    const int*   __restrict__ node_map, // [P, MAXC]
    float*       __restrict__ out)      // [NNODES * B, H]
{
    const int p    = blockIdx.y;
    const int C0   = blockIdx.x * TN;
    const int tid  = threadIdx.x;
    const int lane = tid & 31;
    const int warp = tid >> 5;
    const int g    = lane >> 2;   // groupID  (0..7)
    const int t    = lane & 3;    // tid-in-group (0..3)

    const int warp_m = warp >> 2;          // 0..1 -> 32 M-rows each
    const int warp_n = warp & 3;           // 0..3 -> 16 N-cols each
    const int m_base = warp_m * 32;
    const int n_base = warp_n * 16;

    // smem: hi/lo tf32 copies of A (As[k][m]) and B (Bs[k][c])
    __shared__ __align__(16) float AsHi[TK][SSTR];
    __shared__ __align__(16) float AsLo[TK][SSTR];
    __shared__ __align__(16) float BsHi[TK][SSTR];
    __shared__ __align__(16) float BsLo[TK][SSTR];

    const float*     xp = x + p * Fdim;                       // + b*T*P*F + t*P*F + f
    const float*     Wp = W + (long long)p * Ddim * NCdim;    // [D][576]

    // fill roles
    const int a_m  = tid >> 2;         // 0..63 : batch row loaded by this thread
    const int a_fq = (tid & 3) * 4;    // k-quad within chunk (0,4,8,12)
    const int b_kk = tid >> 4;         // 0..15 : W row within chunk
    const int b_c  = (tid & 15) * 4;   // 0..60 : col quad

    // accumulators: [mtile][ntile][4]
    float acc[2][2][4];
    #pragma unroll
    for (int i = 0; i < 2; i++)
        #pragma unroll
        for (int j = 0; j < 2; j++)
            #pragma unroll
            for (int r = 0; r < 4; r++)
                acc[i][j][r] = 0.0f;

    const long long a_row_off = (long long)a_m * (Tdim * Pdim * Fdim);

    for (int kc = 0; kc < NKC; kc++) {
        const int K0 = kc * TK;
        __syncthreads();   // previous chunk's compute finished

        // ---- fill A: x[a_m, tt, p, f0 + a_fq .. +3] -> As*[a_fq+j][a_m] ----
        {
            const int tt = K0 >> 7;
            const int f0 = K0 & 127;
            float4 v = *reinterpret_cast<const float4*>(
                xp + a_row_off + tt * (Pdim * Fdim) + f0 + a_fq);
            unsigned hi, lo;
            split_tf32(v.x, hi, lo);
            AsHi[a_fq + 0][a_m] = __uint_as_float(hi); AsLo[a_fq + 0][a_m] = __uint_as_float(lo);
            split_tf32(v.y, hi, lo);
            AsHi[a_fq + 1][a_m] = __uint_as_float(hi); AsLo[a_fq + 1][a_m] = __uint_as_float(lo);
            split_tf32(v.z, hi, lo);
            AsHi[a_fq + 2][a_m] = __uint_as_float(hi); AsLo[a_fq + 2][a_m] = __uint_as_float(lo);
            split_tf32(v.w, hi, lo);
            AsHi[a_fq + 3][a_m] = __uint_as_float(hi); AsLo[a_fq + 3][a_m] = __uint_as_float(lo);
        }
        // ---- fill B: W[K0+b_kk, C0+b_c .. +3] -> Bs*[b_kk][b_c..+3] ----
        {
            float4 v = *reinterpret_cast<const float4*>(
                Wp + (long long)(K0 + b_kk) * NCdim + C0 + b_c);
            unsigned h0, l0, h1, l1, h2, l2, h3, l3;
            split_tf32(v.x, h0, l0); split_tf32(v.y, h1, l1);
            split_tf32(v.z, h2, l2); split_tf32(v.w, h3, l3);
            float4 hv = make_float4(__uint_as_float(h0), __uint_as_float(h1),
                                    __uint_as_float(h2), __uint_as_float(h3));
            float4 lv = make_float4(__uint_as_float(l0), __uint_as_float(l1),
                                    __uint_as_float(l2), __uint_as_float(l3));
            *reinterpret_cast<float4*>(&BsHi[b_kk][b_c]) = hv;
            *reinterpret_cast<float4*>(&BsLo[b_kk][b_c]) = lv;
        }
        __syncthreads();

        // ---- compute: two k8 steps ----
        #pragma unroll
        for (int s = 0; s < 2; s++) {
            const int k0 = s * 8;
            // A fragments (m16 x k8), row-major: a0=(g,t) a1=(g+8,t) a2=(g,t+4) a3=(g+8,t+4)
            unsigned aHi[2][4], aLo[2][4];
            #pragma unroll
            for (int i = 0; i < 2; i++) {
                const int m0 = m_base + i * 16;
                aHi[i][0] = __float_as_uint(AsHi[k0 + t    ][m0 + g    ]);
                aHi[i][1] = __float_as_uint(AsHi[k0 + t    ][m0 + g + 8]);
                aHi[i][2] = __float_as_uint(AsHi[k0 + t + 4][m0 + g    ]);
                aHi[i][3] = __float_as_uint(AsHi[k0 + t + 4][m0 + g + 8]);
                aLo[i][0] = __float_as_uint(AsLo[k0 + t    ][m0 + g    ]);
                aLo[i][1] = __float_as_uint(AsLo[k0 + t    ][m0 + g + 8]);
                aLo[i][2] = __float_as_uint(AsLo[k0 + t + 4][m0 + g    ]);
                aLo[i][3] = __float_as_uint(AsLo[k0 + t + 4][m0 + g + 8]);
            }
            // B fragments (k8 x n8), col-major: b0=(t,g) b1=(t+4,g)
            unsigned bHi[2][2], bLo[2][2];
            #pragma unroll
            for (int j = 0; j < 2; j++) {
                const int c0 = n_base + j * 8;
                bHi[j][0] = __float_as_uint(BsHi[k0 + t    ][c0 + g]);
                bHi[j][1] = __float_as_uint(BsHi[k0 + t + 4][c0 + g]);
                bLo[j][0] = __float_as_uint(BsLo[k0 + t    ][c0 + g]);
                bLo[j][1] = __float_as_uint(BsLo[k0 + t + 4][c0 + g]);
            }
            // 3-term split product, all accumulating into the same fp32 C
            #pragma unroll
            for (int i = 0; i < 2; i++)
                #pragma unroll
                for (int j = 0; j < 2; j++) {
                    mma_tf32(acc[i][j], aHi[i], bHi[j]);
                    mma_tf32(acc[i][j], aHi[i], bLo[j]);
                    mma_tf32(acc[i][j], aLo[i], bHi[j]);
                }
        }
    }

    // ---- epilogue: bias + permutation scatter ----
    // C frag mapping: c0=(g,2t) c1=(g,2t+1) c2=(g+8,2t) c3=(g+8,2t+1)
    const int*   nm = node_map + p * MAXC;
    const float* bp = bias + p * NCdim;

    #pragma unroll
    for (int i = 0; i < 2; i++) {
        const int r0 = m_base + i * 16 + g;     // batch row for c0/c1
        const int r1 = r0 + 8;                  // batch row for c2/c3
        #pragma unroll
        for (int j = 0; j < 2; j++) {
            const int cbase = C0 + n_base + j * 8 + 2 * t;
            #pragma unroll
            for (int e = 0; e < 2; e++) {       // the two adjacent columns
                const int c = cbase + e;
                const int n = c / Hdim;
                const int h = c - n * Hdim;
                const int node = nm[n];
                if (node < NNODES) {
                    const float bb = bp[c];
                    out[(node * Bdim + r0) * Hdim + h] = acc[i][j][e]     + bb;
                    out[(node * Bdim + r1) * Hdim + h] = acc[i][j][2 + e] + bb;
                }
            }
        }
    }
}

extern "C" void kernel_launch(void* const* d_in, const int* in_sizes, int n_in,
                              void* d_out, int out_size)
{
    const float* x        = (const float*)d_in[0];  // [B,T,P,F] fp32
    const float* W        = (const float*)d_in[1];  // [P,T*F,MAXC,H] fp32
    const float* bias     = (const float*)d_in[2];  // [P,MAXC,H] fp32
    const int*   node_map = (const int*)d_in[3];    // [P,MAXC] int32
    float*       out      = (float*)d_out;          // [N*B, H] fp32

    dim3 grid(NCdim / TN, Pdim);   // (9, 128)
    dim3 block(NTHREADS);
    patch_readout_tf32x3_kernel<<<grid, block>>>(x, W, bias, node_map, out);
}

// round 5
// speedup vs baseline: 2.1523x; 2.1523x over previous
#include <cuda_runtime.h>
#include <cuda_bf16.h>
#include <cstdint>

// Problem constants: B=64, T=12, P=128, F=128, H=12, MAXC=48
#define Bdim   64
#define Tdim   12
#define Pdim   128
#define Fdim   128
#define Hdim   12
#define MAXC   48
#define Ddim   (Tdim * Fdim)        // 1536 (K)
#define NCdim  (MAXC * Hdim)        // 576  (GEMM N)
#define NNODES 4356

#define TN 64
#define TK 32
#define NKC (Ddim / TK)             // 48
#define NTHREADS 256                // 8 warps: 2(M) x 4(N)
#define ASTR 40                     // bf16 row stride for As[m][k]  (32 + 8 pad)
#define BSTR 72                     // bf16 row stride for Bs[k][c]  (64 + 8 pad)

__device__ __forceinline__ unsigned smem_u32(const void* p) {
    return (unsigned)__cvta_generic_to_shared(p);
}

// split two fp32 into packed bf16 hi / lo pairs (element order: low half = first)
__device__ __forceinline__ void split2(float x, float y, unsigned& hi, unsigned& lo) {
    __nv_bfloat16 hx = __float2bfloat16_rn(x);
    __nv_bfloat16 hy = __float2bfloat16_rn(y);
    __nv_bfloat16 lx = __float2bfloat16_rn(x - __bfloat162float(hx));
    __nv_bfloat16 ly = __float2bfloat16_rn(y - __bfloat162float(hy));
    hi = (unsigned)__bfloat16_as_ushort(hx) | ((unsigned)__bfloat16_as_ushort(hy) << 16);
    lo = (unsigned)__bfloat16_as_ushort(lx) | ((unsigned)__bfloat16_as_ushort(ly) << 16);
}

__device__ __forceinline__ void ldmx4(unsigned* r, unsigned addr) {
    asm volatile("ldmatrix.sync.aligned.m8n8.x4.shared.b16 {%0,%1,%2,%3}, [%4];"
                 : "=r"(r[0]), "=r"(r[1]), "=r"(r[2]), "=r"(r[3]) : "r"(addr));
}
__device__ __forceinline__ void ldmx4t(unsigned* r, unsigned addr) {
    asm volatile("ldmatrix.sync.aligned.m8n8.x4.trans.shared.b16 {%0,%1,%2,%3}, [%4];"
                 : "=r"(r[0]), "=r"(r[1]), "=r"(r[2]), "=r"(r[3]) : "r"(addr));
}

__device__ __forceinline__ void mma_bf16(float* c, const unsigned* a, unsigned b0, unsigned b1) {
    asm volatile(
        "mma.sync.aligned.m16n8k16.row.col.f32.bf16.bf16.f32 "
        "{%0,%1,%2,%3}, {%4,%5,%6,%7}, {%8,%9}, {%0,%1,%2,%3};"
        : "+f"(c[0]), "+f"(c[1]), "+f"(c[2]), "+f"(c[3])
        : "r"(a[0]), "r"(a[1]), "r"(a[2]), "r"(a[3]), "r"(b0), "r"(b1));
}

__global__ __launch_bounds__(NTHREADS, 2)
void patch_readout_bf16x3_kernel(
    const float* __restrict__ x,        // [B, T, P, F]
    const float* __restrict__ W,        // [P, D, MAXC, H] == [P][1536][576]
    const float* __restrict__ bias,     // [P][576]
    const int*   __restrict__ node_map, // [P, MAXC]
    float*       __restrict__ out)      // [NNODES * B, H]
{
    const int p    = blockIdx.y;
    const int C0   = blockIdx.x * TN;
    const int tid  = threadIdx.x;
    const int lane = tid & 31;
    const int warp = tid >> 5;
    const int g    = lane >> 2;
    const int t    = lane & 3;
    const int m_base = (warp >> 2) * 32;   // 2 M-groups of 32 rows
    const int n_base = (warp & 3) * 16;    // 4 N-groups of 16 cols

    // smem: A[m][k] (ldmatrix non-trans), B[k][c] (ldmatrix trans)
    __shared__ __align__(16) __nv_bfloat16 AsHi[2][64][ASTR];
    __shared__ __align__(16) __nv_bfloat16 AsLo[2][64][ASTR];
    __shared__ __align__(16) __nv_bfloat16 BsHi[2][TK][BSTR];
    __shared__ __align__(16) __nv_bfloat16 BsLo[2][TK][BSTR];

    const unsigned aHiB = smem_u32(AsHi), aLoB = smem_u32(AsLo);
    const unsigned bHiB = smem_u32(BsHi), bLoB = smem_u32(BsLo);
    const unsigned ABUF = 64 * ASTR * 2;   // bytes per A buffer
    const unsigned BBUF = TK * BSTR * 2;   // bytes per B buffer

    const float* xp = x + p * Fdim;
    const float* Wp = W + (long long)p * Ddim * NCdim;

    // ---- fill roles ----
    const int a_m  = tid >> 2;          // 0..63 batch row
    const int a_kq = (tid & 3) * 8;     // k octet
    const int b_k  = tid >> 3;          // 0..31 W row within chunk
    const int b_cq = (tid & 7) * 8;     // c octet
    const long long a_row_off = (long long)a_m * (Tdim * Pdim * Fdim);

    // ---- ldmatrix per-lane address terms ----
    const int q  = lane >> 3;           // address-group
    const int j7 = lane & 7;
    // A tiles: q0=(m0-7,k0-7)->a0  q1=(m8-15,k0-7)->a1  q2=(m0-7,k8-15)->a2  q3->a3
    int rowTermA[2];
    {
        const int rq = (q & 1) * 8 + j7;
        const int cq = (q >> 1) * 8;
        rowTermA[0] = (m_base +  0 + rq) * ASTR + cq;
        rowTermA[1] = (m_base + 16 + rq) * ASTR + cq;
    }
    // B tiles (trans): q0=(k0-7,n0-7)->b[0][0]  q1=(k8-15,n0-7)->b[0][1]
    //                  q2=(k0-7,n8-15)->b[1][0] q3=(k8-15,n8-15)->b[1][1]
    const int rowTermB = ((q & 1) * 8 + j7) * BSTR + n_base + (q >> 1) * 8;

    float acc[2][2][4];
    #pragma unroll
    for (int i = 0; i < 2; i++)
        #pragma unroll
        for (int jj = 0; jj < 2; jj++)
            #pragma unroll
            for (int r = 0; r < 4; r++) acc[i][jj][r] = 0.0f;

    float4 av0, av1, bv0, bv1;

    // ---- load chunk kc's gmem data into registers ----
    auto load_chunk = [&](int kc) {
        const int K0 = kc * TK;
        const int tt = K0 >> 7;
        const int f0 = K0 & 127;
        const float* ap = xp + a_row_off + tt * (Pdim * Fdim) + f0 + a_kq;
        av0 = *reinterpret_cast<const float4*>(ap);
        av1 = *reinterpret_cast<const float4*>(ap + 4);
        const float* bp = Wp + (long long)(K0 + b_k) * NCdim + C0 + b_cq;
        bv0 = *reinterpret_cast<const float4*>(bp);
        bv1 = *reinterpret_cast<const float4*>(bp + 4);
    };
    // ---- split + store registers into smem buffer `buf` ----
    auto store_chunk = [&](int buf) {
        unsigned h0, l0, h1, l1, h2, l2, h3, l3;
        split2(av0.x, av0.y, h0, l0); split2(av0.z, av0.w, h1, l1);
        split2(av1.x, av1.y, h2, l2); split2(av1.z, av1.w, h3, l3);
        *reinterpret_cast<uint4*>(&AsHi[buf][a_m][a_kq]) = make_uint4(h0, h1, h2, h3);
        *reinterpret_cast<uint4*>(&AsLo[buf][a_m][a_kq]) = make_uint4(l0, l1, l2, l3);
        split2(bv0.x, bv0.y, h0, l0); split2(bv0.z, bv0.w, h1, l1);
        split2(bv1.x, bv1.y, h2, l2); split2(bv1.z, bv1.w, h3, l3);
        *reinterpret_cast<uint4*>(&BsHi[buf][b_k][b_cq]) = make_uint4(h0, h1, h2, h3);
        *reinterpret_cast<uint4*>(&BsLo[buf][b_k][b_cq]) = make_uint4(l0, l1, l2, l3);
    };

    load_chunk(0);
    store_chunk(0);
    __syncthreads();

    for (int kc = 0; kc < NKC; kc++) {
        const int buf = kc & 1;
        const bool more = (kc + 1 < NKC);
        if (more) load_chunk(kc + 1);

        #pragma unroll
        for (int s = 0; s < 2; s++) {
            const int k0 = s * 16;
            unsigned aH[2][4], aL[2][4], bH[4], bL[4];
            #pragma unroll
            for (int i = 0; i < 2; i++) {
                const unsigned ao = buf * ABUF + (unsigned)(rowTermA[i] + k0) * 2u;
                ldmx4(aH[i], aHiB + ao);
                ldmx4(aL[i], aLoB + ao);
            }
            {
                const unsigned bo = buf * BBUF + (unsigned)(rowTermB + k0 * BSTR) * 2u;
                ldmx4t(bH, bHiB + bo);
                ldmx4t(bL, bLoB + bo);
            }
            #pragma unroll
            for (int i = 0; i < 2; i++)
                #pragma unroll
                for (int jj = 0; jj < 2; jj++) {
                    mma_bf16(acc[i][jj], aH[i], bH[2 * jj], bH[2 * jj + 1]);
                    mma_bf16(acc[i][jj], aH[i], bL[2 * jj], bL[2 * jj + 1]);
                    mma_bf16(acc[i][jj], aL[i], bH[2 * jj], bH[2 * jj + 1]);
                }
        }

        if (more) {
            store_chunk(buf ^ 1);
            __syncthreads();
        }
    }

    // ---- epilogue: bias + permutation scatter ----
    // C frag: c0=(g,2t) c1=(g,2t+1) c2=(g+8,2t) c3=(g+8,2t+1)
    const int*   nm = node_map + p * MAXC;
    const float* bp = bias + p * NCdim;

    #pragma unroll
    for (int i = 0; i < 2; i++) {
        const int r0 = m_base + i * 16 + g;
        const int r1 = r0 + 8;
        #pragma unroll
        for (int jj = 0; jj < 2; jj++) {
            const int cbase = C0 + n_base + jj * 8 + 2 * t;
            #pragma unroll
            for (int e = 0; e < 2; e++) {
                const int c = cbase + e;
                const int n = c / Hdim;
                const int h = c - n * Hdim;
                const int node = nm[n];
                if (node < NNODES) {
                    const float bb = bp[c];
                    out[(node * Bdim + r0) * Hdim + h] = acc[i][jj][e]     + bb;
                    out[(node * Bdim + r1) * Hdim + h] = acc[i][jj][2 + e] + bb;
                }
            }
        }
    }
}

extern "C" void kernel_launch(void* const* d_in, const int* in_sizes, int n_in,
                              void* d_out, int out_size)
{
    const float* x        = (const float*)d_in[0];
    const float* W        = (const float*)d_in[1];
    const float* bias     = (const float*)d_in[2];
    const int*   node_map = (const int*)d_in[3];
    float*       out      = (float*)d_out;

    dim3 grid(NCdim / TN, Pdim);   // (9, 128)
    dim3 block(NTHREADS);
    patch_readout_bf16x3_kernel<<<grid, block>>>(x, W, bias, node_map, out);
}